// round 8
// baseline (speedup 1.0000x reference)
#include <cuda_runtime.h>
#include <math.h>

// BM3D-deblurring: RI filter + global empirical Wiener, Fourier domain.
// v7: = v6 + conjugate-FFT trick in k_row_fused: mirror-row slots run
// conj(DIF(conj(.))), making Wiener pairing element-aligned (zero scatter,
// register-resident even slots, half the mid-section SMEM traffic).

#define MAXPLANES 12
#define INVN (1.0f / 1048576.0f)
#define PHYS(p) ((p) + (((p) >> 6) << 2))   // pad 4 float2 per 64
#define FSTR 1090                           // per-FFT smem stride; 2*FSTR%32==4

static __device__ float2 g_Z[(size_t)MAXPLANES << 20]; // 96 MB packed spectra
static __device__ float2 g_P[1u << 20];                // OTF scratch
static __device__ float2 g_RI[1u << 20];               // RI filter (stored layout)
static __device__ float  g_PSD[1u << 20];              // colored-noise PSD
static __device__ float2 g_tw[1024];                   // W_1024^k

__device__ __forceinline__ int dr4(int i) {            // base-4 digit reversal
    unsigned x = __brev((unsigned)i) >> 22;
    return (int)(((x & 0x155u) << 1) | ((x & 0x2AAu) >> 1));
}
__device__ __forceinline__ float2 cadd(float2 a, float2 b){ return make_float2(a.x+b.x, a.y+b.y); }
__device__ __forceinline__ float2 csub(float2 a, float2 b){ return make_float2(a.x-b.x, a.y-b.y); }
__device__ __forceinline__ float2 cmul(float2 a, float2 b){ return make_float2(a.x*b.x-a.y*b.y, a.x*b.y+a.y*b.x); }
__device__ __forceinline__ float2 cmulj(float2 a, float2 w){ return make_float2(a.x*w.x+a.y*w.y, a.y*w.x-a.x*w.y); }

__device__ __forceinline__ void bf_dif(float2&x0, float2&x1, float2&x2, float2&x3, int e) {
    float2 t0=cadd(x0,x2), t1=csub(x0,x2), t2=cadd(x1,x3), t3=csub(x1,x3);
    float2 u1=make_float2(t1.x+t3.y, t1.y-t3.x);
    float2 u3=make_float2(t1.x-t3.y, t1.y+t3.x);
    x0=cadd(t0,t2);
    float2 u2=csub(t0,t2);
    x1=cmul(u1,g_tw[e]); x2=cmul(u2,g_tw[2*e]); x3=cmul(u3,g_tw[3*e]);
}
__device__ __forceinline__ void bf_dit(float2&x0, float2&x1, float2&x2, float2&x3, int e) {
    float2 a1=cmulj(x1,g_tw[e]), a2=cmulj(x2,g_tw[2*e]), a3=cmulj(x3,g_tw[3*e]);
    float2 t0=cadd(x0,a2), t1=csub(x0,a2), t2=cadd(a1,a3), t3=csub(a1,a3);
    x0=cadd(t0,t2);
    x1=make_float2(t1.x-t3.y, t1.y+t3.x);
    x2=csub(t0,t2);
    x3=make_float2(t1.x+t3.y, t1.y-t3.x);
}

__device__ __forceinline__ void dif_A(float2* x, int t) {
    #pragma unroll
    for (int k0=0;k0<4;k0++) bf_dif(x[k0],x[k0+4],x[k0+8],x[k0+12], t+64*k0);
    #pragma unroll
    for (int k0=0;k0<16;k0+=4) bf_dif(x[k0],x[k0+1],x[k0+2],x[k0+3], 4*t);
}
__device__ __forceinline__ void dif_B(float2* x, int e) {
    #pragma unroll
    for (int b=0;b<4;b++) bf_dif(x[b],x[4+b],x[8+b],x[12+b], (4*b+e)<<4);
    #pragma unroll
    for (int a=0;a<4;a++) bf_dif(x[4*a],x[4*a+1],x[4*a+2],x[4*a+3], e<<6);
}
__device__ __forceinline__ void dit_B(float2* x, int eh) {
    #pragma unroll
    for (int a=0;a<4;a++) bf_dit(x[4*a],x[4*a+1],x[4*a+2],x[4*a+3], eh<<6);
    #pragma unroll
    for (int b=0;b<4;b++) bf_dit(x[b],x[4+b],x[8+b],x[12+b], (4*b+eh)<<4);
}
__device__ __forceinline__ void dit_A(float2* x, int t) {
    #pragma unroll
    for (int k0=0;k0<16;k0+=4) bf_dit(x[k0],x[k0+1],x[k0+2],x[k0+3], t<<2);
    #pragma unroll
    for (int k0=0;k0<4;k0++) bf_dit(x[k0],x[k0+4],x[k0+8],x[k0+12], t+64*k0);
}

__device__ __forceinline__ float2 shx(float2 v, int m) {
    return make_float2(__shfl_xor_sync(0xffffffffu, v.x, m),
                       __shfl_xor_sync(0xffffffffu, v.y, m));
}
template <int M1, int M2>
__device__ __forceinline__ float2 difC(float2 v, int e) {
    float2 p = shx(v, M2);
    float2 A = ((e & 2) == 0) ? cadd(v, p) : csub(p, v);
    float2 q = shx(A, M1);
    if (e == 0) return cadd(A, q);
    if (e == 1) return csub(q, A);
    if (e == 2) return make_float2(A.x + q.y, A.y - q.x);
    return make_float2(q.x - A.y, q.y + A.x);
}
template <int M1, int M2>
__device__ __forceinline__ float2 ditC(float2 v, int e) {
    float2 p = shx(v, M2);
    float2 A = ((e & 2) == 0) ? cadd(v, p) : csub(p, v);
    float2 q = shx(A, M1);
    if (e == 0) return cadd(A, q);
    if (e == 1) return csub(q, A);
    if (e == 2) return make_float2(A.x - q.y, A.y + q.x);
    return make_float2(q.x + A.y, q.y - A.x);
}

// ---------------- init: twiddles + circularly-rolled PSF -----------------
__global__ void k_init(const float* __restrict__ psf, int kh) {
    int idx = blockIdx.x * 256 + threadIdx.x;
    int r = idx >> 10, c = idx & 1023;
    int i = (r + (kh >> 1)) & 1023;
    int j = (c + (kh >> 1)) & 1023;
    float v = (i < kh && j < kh) ? psf[i * kh + j] : 0.f;
    g_P[idx] = make_float2(v, 0.f);
    if (idx < 1024) {
        float sn, cs;
        sincospif(-(float)idx / 512.0f, &sn, &cs);
        g_tw[idx] = make_float2(cs, sn);
    }
}

// ---------------- prep: column DIF on the 25 nonzero PSF columns --------
__global__ void __launch_bounds__(512) k_colP_fast() {
    extern __shared__ float2 sb[];
    int tid = threadIdx.x;
    int f = tid & 7, t = tid >> 3;
    int m = t >> 2, e = t & 3;
    int bx = blockIdx.x;
    int c = (bx < 2) ? (bx * 8 + f) : (1008 + (bx - 2) * 8 + f);
    float2* buf = sb + f * FSTR;
    float2 x[16];
    #pragma unroll
    for (int k=0;k<16;k++) x[k] = g_P[((t+64*k)<<10) + c];
    dif_A(x, t);
    #pragma unroll
    for (int k=0;k<16;k++) buf[PHYS(t+64*k)] = x[k];
    __syncthreads();
    #pragma unroll
    for (int j=0;j<16;j++){ int a=j>>2,b=j&3; x[j]=buf[PHYS(64*m+16*a+4*b+e)]; }
    dif_B(x, e);
    int pe = ((e & 1) << 1) | ((e >> 1) & 1);
    #pragma unroll
    for (int j=0;j<16;j++){
        int a=j>>2, b=j&3;
        g_P[((64*m+16*a+4*b+pe)<<10) + c] = difC<8, 16>(x[j], e);
    }
}

// ---------------- prep: row DIF + RI/PSD from registers ------------------
__global__ void __launch_bounds__(512) k_rowP_ri_fast() {
    extern __shared__ float2 sb[];
    int tid = threadIdx.x;
    int f = tid >> 6, t = tid & 63;
    int m = t >> 2, e = t & 3;
    int row = blockIdx.x * 8 + f;
    float2* buf = sb + f * FSTR;
    size_t gb = (size_t)row << 10;
    float2 x[16];
    #pragma unroll
    for (int k=0;k<16;k++) x[k] = g_P[gb + t + 64*k];
    dif_A(x, t);
    #pragma unroll
    for (int k=0;k<16;k++) buf[PHYS(t+64*k)] = x[k];
    __syncthreads();
    #pragma unroll
    for (int j=0;j<16;j++){ int a=j>>2,b=j&3; x[j]=buf[PHYS(64*m+16*a+4*b+e)]; }
    dif_B(x, e);
    int pe = ((e & 1) << 1) | ((e >> 1) & 1);
    #pragma unroll
    for (int j=0;j<16;j++){
        int a=j>>2, b=j&3;
        float2 h = difC<1, 2>(x[j], e);
        int P = 64*m+16*a+4*b+pe;
        float d = h.x*h.x + h.y*h.y + 0.0025f;
        float inv = 1.0f / d;
        float rx = h.x*inv, ry = -h.y*inv;
        g_RI[gb + P]  = make_float2(rx, ry);
        g_PSD[gb + P] = 0.0025f * (rx*rx + ry*ry) * 1048576.0f;
    }
}

// ---------------- Wiener on a conjugate-mirror pair ----------------------
__device__ __forceinline__ void wiener_pair(float2 z1, float2 z2, int gi,
                                            float2& v1, float2& v2) {
    float2 za = make_float2(0.5f*(z1.x+z2.x), 0.5f*(z1.y-z2.y));
    float2 zb = make_float2(0.5f*(z1.y+z2.y), 0.5f*(z2.x-z1.x));
    float2 ri = g_RI[gi];
    float  pp = g_PSD[gi];
    float2 a = cmul(za, ri);
    float2 b = cmul(zb, ri);
    float Sa = fmaxf((a.x*a.x + a.y*a.y)*INVN - pp, 0.f);
    float Sb = fmaxf((b.x*b.x + b.y*b.y)*INVN - pp, 0.f);
    float wa = Sa / (Sa + pp + 1e-12f);
    float wb = Sb / (Sb + pp + 1e-12f);
    a.x*=wa; a.y*=wa; b.x*=wb; b.y*=wb;
    v1 = make_float2(a.x - b.y, a.y + b.x);
    v2 = make_float2(a.x + b.y, b.x - a.y);
}

// ---------------- pass 1: pack two real images, column DIF (8 cols) -----
__global__ void __launch_bounds__(512) k_col_fwd(const float* __restrict__ y) {
    extern __shared__ float2 sb[];
    int tid = threadIdx.x;
    int f = tid & 7, t = tid >> 3;
    int m = t >> 2, e = t & 3;
    size_t pb = (size_t)blockIdx.y << 20;
    const float* ya = y + (pb << 1);
    const float* yb = ya + (1u << 20);
    int c = (blockIdx.x << 3) + f;
    float2* buf = sb + f * FSTR;
    float2 x[16];
    #pragma unroll
    for (int k=0;k<16;k++){ int r=t+64*k; x[k]=make_float2(ya[(r<<10)+c], yb[(r<<10)+c]); }
    dif_A(x, t);
    #pragma unroll
    for (int k=0;k<16;k++) buf[PHYS(t+64*k)] = x[k];
    __syncthreads();
    #pragma unroll
    for (int j=0;j<16;j++){ int a=j>>2,b=j&3; x[j]=buf[PHYS(64*m+16*a+4*b+e)]; }
    dif_B(x, e);
    int pe = ((e & 1) << 1) | ((e >> 1) & 1);
    #pragma unroll
    for (int j=0;j<16;j++){
        int a=j>>2, b=j&3;
        float2 r = difC<8, 16>(x[j], e);
        g_Z[pb + ((size_t)(64*m+16*a+4*b+pe) << 10) + c] = r;
    }
}

// ---------------- pass 2: row DIF + aligned Wiener + row DIT -------------
// Mirror-row slots (h=1) compute conj(DIF(conj(z))): their stored slot s then
// holds Z_-U(-c) for c=dr4(s), so the conjugate-pair partner of the even
// slot's element is at the SAME position -> aligned, conflict-free pairing.
// Inverse side: y = conj(DIT(conj(W))). Rows {0,512} use the legacy path.
__global__ void __launch_bounds__(256) k_row_fused() {
    __shared__ float2 sb[4 * FSTR];
    int tid = threadIdx.x;
    int f = tid >> 6, t = tid & 63;
    int m = t >> 2, e = t & 3;
    int pe = ((e & 1) << 1) | ((e >> 1) & 1);
    int w = f >> 1, h = f & 1;
    int bx = blockIdx.x;
    size_t pb = (size_t)blockIdx.y << 20;
    int U = 2 * bx + w;
    int row = (U == 0) ? (h ? 2 : 0) : dr4(h ? 1024 - U : U);
    bool legacy = (bx == 0 && w == 0);                 // rows {0,512}
    bool cj = (h == 1) && !legacy;                     // conjugate-trick slot
    float2* buf = sb + f * FSTR;
    size_t gbase = pb + ((size_t)row << 10);
    float2 x[16];
    #pragma unroll
    for (int k=0;k<16;k++){
        x[k] = g_Z[gbase + t + 64*k];
        if (cj) x[k].y = -x[k].y;
    }
    dif_A(x, t);
    #pragma unroll
    for (int k=0;k<16;k++) buf[PHYS(t+64*k)] = x[k];
    __syncthreads();                                   // S1
    #pragma unroll
    for (int j=0;j<16;j++){ int a=j>>2,b=j&3; x[j]=buf[PHYS(64*m+16*a+4*b+e)]; }
    dif_B(x, e);
    #pragma unroll
    for (int j=0;j<16;j++){
        x[j] = difC<1, 2>(x[j], e);
        if (cj) x[j].y = -x[j].y;                      // now Z_-U(-c) at pos P
    }
    __syncthreads();                                   // S2: B-reads done
    if (legacy || h) {
        #pragma unroll
        for (int j=0;j<16;j++){ int a=j>>2,b=j&3; buf[PHYS(64*m+16*a+4*b+pe)] = x[j]; }
    }
    __syncthreads();                                   // S3
    if (bx == 0 && tid < 128) {                        // legacy Wiener, slots 0,1
        for (int l = tid; l < 1026; l += 128) {
            int rw = (l >= 513); int cf = l - 513 * rw;
            int sc = dr4(cf), sm2 = dr4((1024 - cf) & 1023);
            float2 v1, v2;
            int rA = rw ? 2 : 0;
            wiener_pair(sb[rw*FSTR + PHYS(sc)], sb[rw*FSTR + PHYS(sm2)],
                        (rA << 10) + sc, v1, v2);
            sb[rw*FSTR + PHYS(sc)]  = v1;
            sb[rw*FSTR + PHYS(sm2)] = v2;
        }
    } else if (!legacy && h == 0) {                    // aligned reg-resident Wiener
        float2* pbuf = buf + FSTR;                     // partner (odd) slot
        #pragma unroll
        for (int j=0;j<16;j++){
            int a=j>>2, b=j&3;
            int P = 64*m+16*a+4*b+pe;
            float2 z2 = pbuf[PHYS(P)];
            float2 v1, v2;
            wiener_pair(x[j], z2, (row << 10) + P, v1, v2);
            x[j] = v1;
            pbuf[PHYS(P)] = v2;
        }
    }
    __syncthreads();                                   // S4
    if (legacy || h) {
        #pragma unroll
        for (int j=0;j<16;j++){ int a=j>>2,b=j&3; x[j] = buf[PHYS(64*m+16*a+4*b+pe)]; }
    }
    if (cj) {
        #pragma unroll
        for (int j=0;j<16;j++) x[j].y = -x[j].y;       // conj before inverse
    }
    // quad permute pe -> e ownership (swap lanes e=1 and e=2)
    #pragma unroll
    for (int j=0;j<16;j++){
        float2 sw = shx(x[j], 3);
        if (e == 1 || e == 2) x[j] = sw;
    }
    #pragma unroll
    for (int j=0;j<16;j++) x[j] = ditC<1, 2>(x[j], e);
    dit_B(x, pe);
    __syncthreads();                                   // S5
    #pragma unroll
    for (int j=0;j<16;j++){ int a=j>>2,b=j&3; buf[PHYS(64*m+16*a+4*b+pe)] = x[j]; }
    __syncthreads();                                   // S6
    #pragma unroll
    for (int k=0;k<16;k++) x[k] = buf[PHYS(t+64*k)];
    dit_A(x, t);
    #pragma unroll
    for (int k=0;k<16;k++){
        float2 v = x[k];
        if (cj) v.y = -v.y;                            // conj after inverse
        g_Z[gbase + t + 64*k] = v;
    }
}

// ---------------- pass 3: column DIT + unpack real/imag (8 cols) --------
__global__ void __launch_bounds__(512) k_col_inv(float* __restrict__ out) {
    extern __shared__ float2 sb[];
    int tid = threadIdx.x;
    int f = tid & 7, t = tid >> 3;
    int m = t >> 2, e = t & 3;
    size_t pb = (size_t)blockIdx.y << 20;
    float* oa = out + (pb << 1);
    float* ob = oa + (1u << 20);
    int c = (blockIdx.x << 3) + f;
    float2* buf = sb + f * FSTR;
    float2 x[16];
    #pragma unroll
    for (int j=0;j<16;j++){
        int a=j>>2, b=j&3;
        float2 v = g_Z[pb + ((size_t)(64*m+16*a+4*b+e) << 10) + c];
        x[j] = ditC<8, 16>(v, e);
    }
    int pe = ((e & 1) << 1) | ((e >> 1) & 1);
    dit_B(x, pe);
    #pragma unroll
    for (int j=0;j<16;j++){ int a=j>>2,b=j&3; buf[PHYS(64*m+16*a+4*b+pe)] = x[j]; }
    __syncthreads();
    #pragma unroll
    for (int k=0;k<16;k++) x[k] = buf[PHYS(t+64*k)];
    dit_A(x, t);
    #pragma unroll
    for (int k=0;k<16;k++){
        int r = t + 64*k;
        oa[(r<<10)+c] = x[k].x * INVN;
        ob[(r<<10)+c] = x[k].y * INVN;
    }
}

extern "C" void kernel_launch(void* const* d_in, const int* in_sizes, int n_in,
                              void* d_out, int out_size) {
    const float* y   = (const float*)d_in[0];
    const float* psf = (const float*)d_in[1];
    float* out = (float*)d_out;

    int imgs = in_sizes[0] >> 20;                      // 24
    int planes = imgs >> 1;                            // 12 packed complex planes
    if (planes > MAXPLANES) planes = MAXPLANES;
    int kh = (int)lroundf(sqrtf((float)in_sizes[1])); // 25

    const int colSmem = 8 * FSTR * (int)sizeof(float2);   // ~68 KB dynamic
    cudaFuncSetAttribute(k_colP_fast,    cudaFuncAttributeMaxDynamicSharedMemorySize, colSmem);
    cudaFuncSetAttribute(k_rowP_ri_fast, cudaFuncAttributeMaxDynamicSharedMemorySize, colSmem);
    cudaFuncSetAttribute(k_col_fwd,      cudaFuncAttributeMaxDynamicSharedMemorySize, colSmem);
    cudaFuncSetAttribute(k_col_inv,      cudaFuncAttributeMaxDynamicSharedMemorySize, colSmem);

    // OTF -> RI + PSD (stored digit-reversed layout matching main pipeline)
    k_init<<<4096, 256>>>(psf, kh);
    k_colP_fast<<<4, 512, colSmem>>>();                // only 25 PSF cols nonzero
    k_rowP_ri_fast<<<128, 512, colSmem>>>();

    // main: col DIF -> fused(row DIF, aligned Wiener, row DIT) -> col DIT
    k_col_fwd<<<dim3(128, planes), 512, colSmem>>>(y);
    k_row_fused<<<dim3(256, planes), 256>>>();
    k_col_inv<<<dim3(128, planes), 512, colSmem>>>(out);
}

// round 9
// speedup vs baseline: 1.1213x; 1.1213x over previous
#include <cuda_runtime.h>
#include <math.h>

// BM3D-deblurring: RI filter + global empirical Wiener, Fourier domain.
// v8: = v6 skeleton (proven 284.7us) with conjugate-FFT alignment in the
// row_fused Wiener loop: odd (mirror-row) slots run conj(DIF(conj(.))), so
// the pair partner sits at the SAME aligned SMEM position -> the Wiener loop
// is scatter-free and dr4-free. Symmetric all-SMEM flow, no shuffles added.

#define MAXPLANES 12
#define INVN (1.0f / 1048576.0f)
#define PHYS(p) ((p) + (((p) >> 6) << 2))   // pad 4 float2 per 64
#define FSTR 1090                           // per-FFT smem stride; 2*FSTR%32==4

static __device__ float2 g_Z[(size_t)MAXPLANES << 20]; // 96 MB packed spectra
static __device__ float2 g_P[1u << 20];                // OTF scratch
static __device__ float2 g_RI[1u << 20];               // RI filter (stored layout)
static __device__ float  g_PSD[1u << 20];              // colored-noise PSD
static __device__ float2 g_tw[1024];                   // W_1024^k

__device__ __forceinline__ int dr4(int i) {            // base-4 digit reversal
    unsigned x = __brev((unsigned)i) >> 22;
    return (int)(((x & 0x155u) << 1) | ((x & 0x2AAu) >> 1));
}
__device__ __forceinline__ float2 cadd(float2 a, float2 b){ return make_float2(a.x+b.x, a.y+b.y); }
__device__ __forceinline__ float2 csub(float2 a, float2 b){ return make_float2(a.x-b.x, a.y-b.y); }
__device__ __forceinline__ float2 cmul(float2 a, float2 b){ return make_float2(a.x*b.x-a.y*b.y, a.x*b.y+a.y*b.x); }
__device__ __forceinline__ float2 cmulj(float2 a, float2 w){ return make_float2(a.x*w.x+a.y*w.y, a.y*w.x-a.x*w.y); }

__device__ __forceinline__ void bf_dif(float2&x0, float2&x1, float2&x2, float2&x3, int e) {
    float2 t0=cadd(x0,x2), t1=csub(x0,x2), t2=cadd(x1,x3), t3=csub(x1,x3);
    float2 u1=make_float2(t1.x+t3.y, t1.y-t3.x);
    float2 u3=make_float2(t1.x-t3.y, t1.y+t3.x);
    x0=cadd(t0,t2);
    float2 u2=csub(t0,t2);
    x1=cmul(u1,g_tw[e]); x2=cmul(u2,g_tw[2*e]); x3=cmul(u3,g_tw[3*e]);
}
__device__ __forceinline__ void bf_dit(float2&x0, float2&x1, float2&x2, float2&x3, int e) {
    float2 a1=cmulj(x1,g_tw[e]), a2=cmulj(x2,g_tw[2*e]), a3=cmulj(x3,g_tw[3*e]);
    float2 t0=cadd(x0,a2), t1=csub(x0,a2), t2=cadd(a1,a3), t3=csub(a1,a3);
    x0=cadd(t0,t2);
    x1=make_float2(t1.x-t3.y, t1.y+t3.x);
    x2=csub(t0,t2);
    x3=make_float2(t1.x+t3.y, t1.y-t3.x);
}

__device__ __forceinline__ void dif_A(float2* x, int t) {
    #pragma unroll
    for (int k0=0;k0<4;k0++) bf_dif(x[k0],x[k0+4],x[k0+8],x[k0+12], t+64*k0);
    #pragma unroll
    for (int k0=0;k0<16;k0+=4) bf_dif(x[k0],x[k0+1],x[k0+2],x[k0+3], 4*t);
}
__device__ __forceinline__ void dif_B(float2* x, int e) {
    #pragma unroll
    for (int b=0;b<4;b++) bf_dif(x[b],x[4+b],x[8+b],x[12+b], (4*b+e)<<4);
    #pragma unroll
    for (int a=0;a<4;a++) bf_dif(x[4*a],x[4*a+1],x[4*a+2],x[4*a+3], e<<6);
}
__device__ __forceinline__ void dit_B(float2* x, int eh) {
    #pragma unroll
    for (int a=0;a<4;a++) bf_dit(x[4*a],x[4*a+1],x[4*a+2],x[4*a+3], eh<<6);
    #pragma unroll
    for (int b=0;b<4;b++) bf_dit(x[b],x[4+b],x[8+b],x[12+b], (4*b+eh)<<4);
}
__device__ __forceinline__ void dit_A(float2* x, int t) {
    #pragma unroll
    for (int k0=0;k0<16;k0+=4) bf_dit(x[k0],x[k0+1],x[k0+2],x[k0+3], t<<2);
    #pragma unroll
    for (int k0=0;k0<4;k0++) bf_dit(x[k0],x[k0+4],x[k0+8],x[k0+12], t+64*k0);
}

__device__ __forceinline__ float2 shx(float2 v, int m) {
    return make_float2(__shfl_xor_sync(0xffffffffu, v.x, m),
                       __shfl_xor_sync(0xffffffffu, v.y, m));
}
template <int M1, int M2>
__device__ __forceinline__ float2 difC(float2 v, int e) {
    float2 p = shx(v, M2);
    float2 A = ((e & 2) == 0) ? cadd(v, p) : csub(p, v);
    float2 q = shx(A, M1);
    if (e == 0) return cadd(A, q);
    if (e == 1) return csub(q, A);
    if (e == 2) return make_float2(A.x + q.y, A.y - q.x);
    return make_float2(q.x - A.y, q.y + A.x);
}
template <int M1, int M2>
__device__ __forceinline__ float2 ditC(float2 v, int e) {
    float2 p = shx(v, M2);
    float2 A = ((e & 2) == 0) ? cadd(v, p) : csub(p, v);
    float2 q = shx(A, M1);
    if (e == 0) return cadd(A, q);
    if (e == 1) return csub(q, A);
    if (e == 2) return make_float2(A.x - q.y, A.y + q.x);
    return make_float2(q.x + A.y, q.y - A.x);
}

// ---------------- init: twiddles + circularly-rolled PSF -----------------
__global__ void k_init(const float* __restrict__ psf, int kh) {
    int idx = blockIdx.x * 256 + threadIdx.x;
    int r = idx >> 10, c = idx & 1023;
    int i = (r + (kh >> 1)) & 1023;
    int j = (c + (kh >> 1)) & 1023;
    float v = (i < kh && j < kh) ? psf[i * kh + j] : 0.f;
    g_P[idx] = make_float2(v, 0.f);
    if (idx < 1024) {
        float sn, cs;
        sincospif(-(float)idx / 512.0f, &sn, &cs);
        g_tw[idx] = make_float2(cs, sn);
    }
}

// ---------------- prep: column DIF on the 25 nonzero PSF columns --------
__global__ void __launch_bounds__(512) k_colP_fast() {
    extern __shared__ float2 sb[];
    int tid = threadIdx.x;
    int f = tid & 7, t = tid >> 3;
    int m = t >> 2, e = t & 3;
    int bx = blockIdx.x;
    int c = (bx < 2) ? (bx * 8 + f) : (1008 + (bx - 2) * 8 + f);
    float2* buf = sb + f * FSTR;
    float2 x[16];
    #pragma unroll
    for (int k=0;k<16;k++) x[k] = g_P[((t+64*k)<<10) + c];
    dif_A(x, t);
    #pragma unroll
    for (int k=0;k<16;k++) buf[PHYS(t+64*k)] = x[k];
    __syncthreads();
    #pragma unroll
    for (int j=0;j<16;j++){ int a=j>>2,b=j&3; x[j]=buf[PHYS(64*m+16*a+4*b+e)]; }
    dif_B(x, e);
    int pe = ((e & 1) << 1) | ((e >> 1) & 1);
    #pragma unroll
    for (int j=0;j<16;j++){
        int a=j>>2, b=j&3;
        g_P[((64*m+16*a+4*b+pe)<<10) + c] = difC<8, 16>(x[j], e);
    }
}

// ---------------- prep: row DIF + RI/PSD from registers ------------------
__global__ void __launch_bounds__(512) k_rowP_ri_fast() {
    extern __shared__ float2 sb[];
    int tid = threadIdx.x;
    int f = tid >> 6, t = tid & 63;
    int m = t >> 2, e = t & 3;
    int row = blockIdx.x * 8 + f;
    float2* buf = sb + f * FSTR;
    size_t gb = (size_t)row << 10;
    float2 x[16];
    #pragma unroll
    for (int k=0;k<16;k++) x[k] = g_P[gb + t + 64*k];
    dif_A(x, t);
    #pragma unroll
    for (int k=0;k<16;k++) buf[PHYS(t+64*k)] = x[k];
    __syncthreads();
    #pragma unroll
    for (int j=0;j<16;j++){ int a=j>>2,b=j&3; x[j]=buf[PHYS(64*m+16*a+4*b+e)]; }
    dif_B(x, e);
    int pe = ((e & 1) << 1) | ((e >> 1) & 1);
    #pragma unroll
    for (int j=0;j<16;j++){
        int a=j>>2, b=j&3;
        float2 h = difC<1, 2>(x[j], e);
        int P = 64*m+16*a+4*b+pe;
        float d = h.x*h.x + h.y*h.y + 0.0025f;
        float inv = 1.0f / d;
        float rx = h.x*inv, ry = -h.y*inv;
        g_RI[gb + P]  = make_float2(rx, ry);
        g_PSD[gb + P] = 0.0025f * (rx*rx + ry*ry) * 1048576.0f;
    }
}

// ---------------- Wiener on a conjugate-mirror pair ----------------------
__device__ __forceinline__ void wiener_pair(float2 z1, float2 z2, int gi,
                                            float2& v1, float2& v2) {
    float2 za = make_float2(0.5f*(z1.x+z2.x), 0.5f*(z1.y-z2.y));
    float2 zb = make_float2(0.5f*(z1.y+z2.y), 0.5f*(z2.x-z1.x));
    float2 ri = g_RI[gi];
    float  pp = g_PSD[gi];
    float2 a = cmul(za, ri);
    float2 b = cmul(zb, ri);
    float Sa = fmaxf((a.x*a.x + a.y*a.y)*INVN - pp, 0.f);
    float Sb = fmaxf((b.x*b.x + b.y*b.y)*INVN - pp, 0.f);
    float wa = Sa / (Sa + pp + 1e-12f);
    float wb = Sb / (Sb + pp + 1e-12f);
    a.x*=wa; a.y*=wa; b.x*=wb; b.y*=wb;
    v1 = make_float2(a.x - b.y, a.y + b.x);
    v2 = make_float2(a.x + b.y, b.x - a.y);
}

// ---------------- pass 1: pack two real images, column DIF (8 cols) -----
__global__ void __launch_bounds__(512) k_col_fwd(const float* __restrict__ y) {
    extern __shared__ float2 sb[];
    int tid = threadIdx.x;
    int f = tid & 7, t = tid >> 3;
    int m = t >> 2, e = t & 3;
    size_t pb = (size_t)blockIdx.y << 20;
    const float* ya = y + (pb << 1);
    const float* yb = ya + (1u << 20);
    int c = (blockIdx.x << 3) + f;
    float2* buf = sb + f * FSTR;
    float2 x[16];
    #pragma unroll
    for (int k=0;k<16;k++){ int r=t+64*k; x[k]=make_float2(ya[(r<<10)+c], yb[(r<<10)+c]); }
    dif_A(x, t);
    #pragma unroll
    for (int k=0;k<16;k++) buf[PHYS(t+64*k)] = x[k];
    __syncthreads();
    #pragma unroll
    for (int j=0;j<16;j++){ int a=j>>2,b=j&3; x[j]=buf[PHYS(64*m+16*a+4*b+e)]; }
    dif_B(x, e);
    int pe = ((e & 1) << 1) | ((e >> 1) & 1);
    #pragma unroll
    for (int j=0;j<16;j++){
        int a=j>>2, b=j&3;
        float2 r = difC<8, 16>(x[j], e);
        g_Z[pb + ((size_t)(64*m+16*a+4*b+pe) << 10) + c] = r;
    }
}

// ---------------- pass 2: row DIF + ALIGNED Wiener + row DIT -------------
// Odd (mirror-row) slots compute conj(DIF(conj(z))): their stored position P
// then holds Z_-U(-c(P)), i.e. the conjugate-pair partner of the even slot's
// element at the SAME position P. The Wiener loop is linear & conflict-free.
// Inverse: odd slots run conj(DIT(conj(.))). Rows {0,512} use the legacy path.
__global__ void __launch_bounds__(256) k_row_fused() {
    __shared__ float2 sb[4 * FSTR];
    int tid = threadIdx.x;
    int f = tid >> 6, t = tid & 63;
    int m = t >> 2, e = t & 3;
    int pe = ((e & 1) << 1) | ((e >> 1) & 1);
    int w = f >> 1, h = f & 1;
    int bx = blockIdx.x;
    size_t pb = (size_t)blockIdx.y << 20;
    int U = 2 * bx + w;
    int row = (U == 0) ? (h ? 2 : 0) : dr4(h ? 1024 - U : U);
    bool legacy = (bx == 0 && w == 0);                 // rows {0,512}
    bool cj = (h == 1) && !legacy;                     // conjugate-trick slot
    float2* buf = sb + f * FSTR;
    size_t gbase = pb + ((size_t)row << 10);
    float2 x[16];
    #pragma unroll
    for (int k=0;k<16;k++){
        x[k] = g_Z[gbase + t + 64*k];
        if (cj) x[k].y = -x[k].y;
    }
    dif_A(x, t);
    #pragma unroll
    for (int k=0;k<16;k++) buf[PHYS(t+64*k)] = x[k];
    __syncthreads();                                   // S1
    #pragma unroll
    for (int j=0;j<16;j++){ int a=j>>2,b=j&3; x[j]=buf[PHYS(64*m+16*a+4*b+e)]; }
    dif_B(x, e);
    __syncthreads();                                   // S2: B-reads done
    #pragma unroll
    for (int j=0;j<16;j++){
        int a=j>>2, b=j&3;
        float2 v = difC<1, 2>(x[j], e);
        if (cj) v.y = -v.y;                            // slot holds Z_-U(-c) at P
        buf[PHYS(64*m+16*a+4*b+pe)] = v;
    }
    __syncthreads();                                   // S3
    // ---- aligned Wiener: partner at the SAME position in the odd slot ----
    for (int l = tid; l < 2048; l += 256) {
        int ww = l >> 10, p = l & 1023;
        if (bx == 0 && ww == 0) continue;              // legacy handled below
        int Ue = 2 * bx + ww;
        int rA = dr4(Ue);
        float2 v1, v2;
        wiener_pair(sb[(2*ww)*FSTR + PHYS(p)], sb[(2*ww+1)*FSTR + PHYS(p)],
                    (rA << 10) + p, v1, v2);
        sb[(2*ww)*FSTR + PHYS(p)]   = v1;
        sb[(2*ww+1)*FSTR + PHYS(p)] = v2;
    }
    if (bx == 0) {                                     // rows {0,512}: self-mirrored
        for (int l = tid; l < 1026; l += 256) {
            int rw = (l >= 513); int cf = l - 513 * rw;
            int sc = dr4(cf), smc = dr4((1024 - cf) & 1023);
            float2 v1, v2;
            int rA = rw ? 2 : 0;
            wiener_pair(sb[rw*FSTR + PHYS(sc)], sb[rw*FSTR + PHYS(smc)],
                        (rA << 10) + sc, v1, v2);
            sb[rw*FSTR + PHYS(sc)]  = v1;
            sb[rw*FSTR + PHYS(smc)] = v2;
        }
    }
    __syncthreads();                                   // S4
    #pragma unroll
    for (int j=0;j<16;j++){
        int a=j>>2, b=j&3;
        float2 v = buf[PHYS(64*m+16*a+4*b+e)];
        if (cj) v.y = -v.y;                            // conj before inverse
        x[j] = ditC<1, 2>(v, e);
    }
    dit_B(x, pe);
    __syncthreads();                                   // S5
    #pragma unroll
    for (int j=0;j<16;j++){ int a=j>>2,b=j&3; buf[PHYS(64*m+16*a+4*b+pe)] = x[j]; }
    __syncthreads();                                   // S6
    #pragma unroll
    for (int k=0;k<16;k++) x[k] = buf[PHYS(t+64*k)];
    dit_A(x, t);
    #pragma unroll
    for (int k=0;k<16;k++){
        float2 v = x[k];
        if (cj) v.y = -v.y;                            // conj after inverse
        g_Z[gbase + t + 64*k] = v;
    }
}

// ---------------- pass 3: column DIT + unpack real/imag (8 cols) --------
__global__ void __launch_bounds__(512) k_col_inv(float* __restrict__ out) {
    extern __shared__ float2 sb[];
    int tid = threadIdx.x;
    int f = tid & 7, t = tid >> 3;
    int m = t >> 2, e = t & 3;
    size_t pb = (size_t)blockIdx.y << 20;
    float* oa = out + (pb << 1);
    float* ob = oa + (1u << 20);
    int c = (blockIdx.x << 3) + f;
    float2* buf = sb + f * FSTR;
    float2 x[16];
    #pragma unroll
    for (int j=0;j<16;j++){
        int a=j>>2, b=j&3;
        float2 v = g_Z[pb + ((size_t)(64*m+16*a+4*b+e) << 10) + c];
        x[j] = ditC<8, 16>(v, e);
    }
    int pe = ((e & 1) << 1) | ((e >> 1) & 1);
    dit_B(x, pe);
    #pragma unroll
    for (int j=0;j<16;j++){ int a=j>>2,b=j&3; buf[PHYS(64*m+16*a+4*b+pe)] = x[j]; }
    __syncthreads();
    #pragma unroll
    for (int k=0;k<16;k++) x[k] = buf[PHYS(t+64*k)];
    dit_A(x, t);
    #pragma unroll
    for (int k=0;k<16;k++){
        int r = t + 64*k;
        oa[(r<<10)+c] = x[k].x * INVN;
        ob[(r<<10)+c] = x[k].y * INVN;
    }
}

extern "C" void kernel_launch(void* const* d_in, const int* in_sizes, int n_in,
                              void* d_out, int out_size) {
    const float* y   = (const float*)d_in[0];
    const float* psf = (const float*)d_in[1];
    float* out = (float*)d_out;

    int imgs = in_sizes[0] >> 20;                      // 24
    int planes = imgs >> 1;                            // 12 packed complex planes
    if (planes > MAXPLANES) planes = MAXPLANES;
    int kh = (int)lroundf(sqrtf((float)in_sizes[1])); // 25

    const int colSmem = 8 * FSTR * (int)sizeof(float2);   // ~68 KB dynamic
    cudaFuncSetAttribute(k_colP_fast,    cudaFuncAttributeMaxDynamicSharedMemorySize, colSmem);
    cudaFuncSetAttribute(k_rowP_ri_fast, cudaFuncAttributeMaxDynamicSharedMemorySize, colSmem);
    cudaFuncSetAttribute(k_col_fwd,      cudaFuncAttributeMaxDynamicSharedMemorySize, colSmem);
    cudaFuncSetAttribute(k_col_inv,      cudaFuncAttributeMaxDynamicSharedMemorySize, colSmem);

    // OTF -> RI + PSD (stored digit-reversed layout matching main pipeline)
    k_init<<<4096, 256>>>(psf, kh);
    k_colP_fast<<<4, 512, colSmem>>>();                // only 25 PSF cols nonzero
    k_rowP_ri_fast<<<128, 512, colSmem>>>();

    // main: col DIF -> fused(row DIF, aligned Wiener, row DIT) -> col DIT
    k_col_fwd<<<dim3(128, planes), 512, colSmem>>>(y);
    k_row_fused<<<dim3(256, planes), 256>>>();
    k_col_inv<<<dim3(128, planes), 512, colSmem>>>(out);
}

// round 10
// speedup vs baseline: 1.1786x; 1.0511x over previous
#include <cuda_runtime.h>
#include <math.h>

// BM3D-deblurring: RI filter + global empirical Wiener, Fourier domain.
// v9: = v8 minus provably-unneeded syncs S2/S5 (B-read vs C-write hazards are
// always intra-quad -> intra-warp), + reverse plane order in row_fused for L2
// reuse of freshly written g_Z, + compact PSF prep (g_Pc[1024][32], no big
// g_P array, k_init = twiddles only).

#define MAXPLANES 12
#define INVN (1.0f / 1048576.0f)
#define PHYS(p) ((p) + (((p) >> 6) << 2))   // pad 4 float2 per 64
#define FSTR 1090                           // per-FFT smem stride; 2*FSTR%32==4

static __device__ float2 g_Z[(size_t)MAXPLANES << 20]; // 96 MB packed spectra
static __device__ float2 g_Pc[1024][32];               // compact OTF scratch
static __device__ float2 g_RI[1u << 20];               // RI filter (stored layout)
static __device__ float  g_PSD[1u << 20];              // colored-noise PSD
static __device__ float2 g_tw[1024];                   // W_1024^k

__device__ __forceinline__ int dr4(int i) {            // base-4 digit reversal
    unsigned x = __brev((unsigned)i) >> 22;
    return (int)(((x & 0x155u) << 1) | ((x & 0x2AAu) >> 1));
}
__device__ __forceinline__ float2 cadd(float2 a, float2 b){ return make_float2(a.x+b.x, a.y+b.y); }
__device__ __forceinline__ float2 csub(float2 a, float2 b){ return make_float2(a.x-b.x, a.y-b.y); }
__device__ __forceinline__ float2 cmul(float2 a, float2 b){ return make_float2(a.x*b.x-a.y*b.y, a.x*b.y+a.y*b.x); }
__device__ __forceinline__ float2 cmulj(float2 a, float2 w){ return make_float2(a.x*w.x+a.y*w.y, a.y*w.x-a.x*w.y); }

__device__ __forceinline__ void bf_dif(float2&x0, float2&x1, float2&x2, float2&x3, int e) {
    float2 t0=cadd(x0,x2), t1=csub(x0,x2), t2=cadd(x1,x3), t3=csub(x1,x3);
    float2 u1=make_float2(t1.x+t3.y, t1.y-t3.x);
    float2 u3=make_float2(t1.x-t3.y, t1.y+t3.x);
    x0=cadd(t0,t2);
    float2 u2=csub(t0,t2);
    x1=cmul(u1,g_tw[e]); x2=cmul(u2,g_tw[2*e]); x3=cmul(u3,g_tw[3*e]);
}
__device__ __forceinline__ void bf_dit(float2&x0, float2&x1, float2&x2, float2&x3, int e) {
    float2 a1=cmulj(x1,g_tw[e]), a2=cmulj(x2,g_tw[2*e]), a3=cmulj(x3,g_tw[3*e]);
    float2 t0=cadd(x0,a2), t1=csub(x0,a2), t2=cadd(a1,a3), t3=csub(a1,a3);
    x0=cadd(t0,t2);
    x1=make_float2(t1.x-t3.y, t1.y+t3.x);
    x2=csub(t0,t2);
    x3=make_float2(t1.x+t3.y, t1.y-t3.x);
}

__device__ __forceinline__ void dif_A(float2* x, int t) {
    #pragma unroll
    for (int k0=0;k0<4;k0++) bf_dif(x[k0],x[k0+4],x[k0+8],x[k0+12], t+64*k0);
    #pragma unroll
    for (int k0=0;k0<16;k0+=4) bf_dif(x[k0],x[k0+1],x[k0+2],x[k0+3], 4*t);
}
__device__ __forceinline__ void dif_B(float2* x, int e) {
    #pragma unroll
    for (int b=0;b<4;b++) bf_dif(x[b],x[4+b],x[8+b],x[12+b], (4*b+e)<<4);
    #pragma unroll
    for (int a=0;a<4;a++) bf_dif(x[4*a],x[4*a+1],x[4*a+2],x[4*a+3], e<<6);
}
__device__ __forceinline__ void dit_B(float2* x, int eh) {
    #pragma unroll
    for (int a=0;a<4;a++) bf_dit(x[4*a],x[4*a+1],x[4*a+2],x[4*a+3], eh<<6);
    #pragma unroll
    for (int b=0;b<4;b++) bf_dit(x[b],x[4+b],x[8+b],x[12+b], (4*b+eh)<<4);
}
__device__ __forceinline__ void dit_A(float2* x, int t) {
    #pragma unroll
    for (int k0=0;k0<16;k0+=4) bf_dit(x[k0],x[k0+1],x[k0+2],x[k0+3], t<<2);
    #pragma unroll
    for (int k0=0;k0<4;k0++) bf_dit(x[k0],x[k0+4],x[k0+8],x[k0+12], t+64*k0);
}

__device__ __forceinline__ float2 shx(float2 v, int m) {
    return make_float2(__shfl_xor_sync(0xffffffffu, v.x, m),
                       __shfl_xor_sync(0xffffffffu, v.y, m));
}
template <int M1, int M2>
__device__ __forceinline__ float2 difC(float2 v, int e) {
    float2 p = shx(v, M2);
    float2 A = ((e & 2) == 0) ? cadd(v, p) : csub(p, v);
    float2 q = shx(A, M1);
    if (e == 0) return cadd(A, q);
    if (e == 1) return csub(q, A);
    if (e == 2) return make_float2(A.x + q.y, A.y - q.x);
    return make_float2(q.x - A.y, q.y + A.x);
}
template <int M1, int M2>
__device__ __forceinline__ float2 ditC(float2 v, int e) {
    float2 p = shx(v, M2);
    float2 A = ((e & 2) == 0) ? cadd(v, p) : csub(p, v);
    float2 q = shx(A, M1);
    if (e == 0) return cadd(A, q);
    if (e == 1) return csub(q, A);
    if (e == 2) return make_float2(A.x - q.y, A.y + q.x);
    return make_float2(q.x + A.y, q.y - A.x);
}

// ---------------- init: twiddles only ------------------------------------
__global__ void k_init() {
    int idx = blockIdx.x * 256 + threadIdx.x;
    if (idx < 1024) {
        float sn, cs;
        sincospif(-(float)idx / 512.0f, &sn, &cs);
        g_tw[idx] = make_float2(cs, sn);
    }
}

// ---------------- prep: column DIF on the 32-col nonzero PSF band -------
// Rolled PSF is nonzero only at rows/cols {0..kh2-? .. } within the 32-col
// band {0..15} U {1008..1023}; positions map to x[0] (t<=kh-1-kh2) and
// x[15] (t >= 64-kh2) only. Output stored compact: g_Pc[pos][c & 31].
__global__ void __launch_bounds__(512) k_colP_fast(const float* __restrict__ psf, int kh) {
    extern __shared__ float2 sb[];
    int tid = threadIdx.x;
    int f = tid & 7, t = tid >> 3;
    int m = t >> 2, e = t & 3;
    int bx = blockIdx.x;
    int c = (bx < 2) ? (bx * 8 + f) : (1008 + (bx - 2) * 8 + f);
    int cidx = c & 31;
    int kh2 = kh >> 1;
    int j = (c + kh2) & 1023;
    float2* buf = sb + f * FSTR;
    float2 x[16];
    #pragma unroll
    for (int k=0;k<16;k++) x[k] = make_float2(0.f, 0.f);
    if (j < kh) {
        int i0 = t + kh2;                 // row index for position t (k=0)
        if (i0 < kh) x[0].x = psf[i0 * kh + j];
        int i15 = t - (64 - kh2);         // row index for position t+960 (k=15)
        if (i15 >= 0) x[15].x = psf[i15 * kh + j];
    }
    dif_A(x, t);
    #pragma unroll
    for (int k=0;k<16;k++) buf[PHYS(t+64*k)] = x[k];
    __syncthreads();
    #pragma unroll
    for (int jj=0;jj<16;jj++){ int a=jj>>2,b=jj&3; x[jj]=buf[PHYS(64*m+16*a+4*b+e)]; }
    dif_B(x, e);
    int pe = ((e & 1) << 1) | ((e >> 1) & 1);
    #pragma unroll
    for (int jj=0;jj<16;jj++){
        int a=jj>>2, b=jj&3;
        g_Pc[64*m+16*a+4*b+pe][cidx] = difC<8, 16>(x[jj], e);
    }
}

// ---------------- prep: row DIF (32 nonzero cols) + RI/PSD --------------
__global__ void __launch_bounds__(512) k_rowP_ri_fast() {
    extern __shared__ float2 sb[];
    int tid = threadIdx.x;
    int f = tid >> 6, t = tid & 63;
    int m = t >> 2, e = t & 3;
    int row = blockIdx.x * 8 + f;
    float2* buf = sb + f * FSTR;
    size_t gb = (size_t)row << 10;
    float2 x[16];
    #pragma unroll
    for (int k=0;k<16;k++) x[k] = make_float2(0.f, 0.f);
    if (t < 16) x[0]  = g_Pc[row][t];           // cols 0..15
    if (t >= 48) x[15] = g_Pc[row][(t + 960) & 31];  // cols 1008..1023
    dif_A(x, t);
    #pragma unroll
    for (int k=0;k<16;k++) buf[PHYS(t+64*k)] = x[k];
    __syncthreads();
    #pragma unroll
    for (int j=0;j<16;j++){ int a=j>>2,b=j&3; x[j]=buf[PHYS(64*m+16*a+4*b+e)]; }
    dif_B(x, e);
    int pe = ((e & 1) << 1) | ((e >> 1) & 1);
    #pragma unroll
    for (int j=0;j<16;j++){
        int a=j>>2, b=j&3;
        float2 h = difC<1, 2>(x[j], e);
        int P = 64*m+16*a+4*b+pe;
        float d = h.x*h.x + h.y*h.y + 0.0025f;
        float inv = 1.0f / d;
        float rx = h.x*inv, ry = -h.y*inv;
        g_RI[gb + P]  = make_float2(rx, ry);
        g_PSD[gb + P] = 0.0025f * (rx*rx + ry*ry) * 1048576.0f;
    }
}

// ---------------- Wiener on a conjugate-mirror pair ----------------------
__device__ __forceinline__ void wiener_pair(float2 z1, float2 z2, int gi,
                                            float2& v1, float2& v2) {
    float2 za = make_float2(0.5f*(z1.x+z2.x), 0.5f*(z1.y-z2.y));
    float2 zb = make_float2(0.5f*(z1.y+z2.y), 0.5f*(z2.x-z1.x));
    float2 ri = g_RI[gi];
    float  pp = g_PSD[gi];
    float2 a = cmul(za, ri);
    float2 b = cmul(zb, ri);
    float Sa = fmaxf((a.x*a.x + a.y*a.y)*INVN - pp, 0.f);
    float Sb = fmaxf((b.x*b.x + b.y*b.y)*INVN - pp, 0.f);
    float wa = Sa / (Sa + pp + 1e-12f);
    float wb = Sb / (Sb + pp + 1e-12f);
    a.x*=wa; a.y*=wa; b.x*=wb; b.y*=wb;
    v1 = make_float2(a.x - b.y, a.y + b.x);
    v2 = make_float2(a.x + b.y, b.x - a.y);
}

// ---------------- pass 1: pack two real images, column DIF (8 cols) -----
__global__ void __launch_bounds__(512) k_col_fwd(const float* __restrict__ y) {
    extern __shared__ float2 sb[];
    int tid = threadIdx.x;
    int f = tid & 7, t = tid >> 3;
    int m = t >> 2, e = t & 3;
    size_t pb = (size_t)blockIdx.y << 20;
    const float* ya = y + (pb << 1);
    const float* yb = ya + (1u << 20);
    int c = (blockIdx.x << 3) + f;
    float2* buf = sb + f * FSTR;
    float2 x[16];
    #pragma unroll
    for (int k=0;k<16;k++){ int r=t+64*k; x[k]=make_float2(ya[(r<<10)+c], yb[(r<<10)+c]); }
    dif_A(x, t);
    #pragma unroll
    for (int k=0;k<16;k++) buf[PHYS(t+64*k)] = x[k];
    __syncthreads();
    #pragma unroll
    for (int j=0;j<16;j++){ int a=j>>2,b=j&3; x[j]=buf[PHYS(64*m+16*a+4*b+e)]; }
    dif_B(x, e);
    int pe = ((e & 1) << 1) | ((e >> 1) & 1);
    #pragma unroll
    for (int j=0;j<16;j++){
        int a=j>>2, b=j&3;
        float2 r = difC<8, 16>(x[j], e);
        g_Z[pb + ((size_t)(64*m+16*a+4*b+pe) << 10) + c] = r;
    }
}

// ---------------- pass 2: row DIF + ALIGNED Wiener + row DIT -------------
// Odd (mirror-row) slots compute conj(DIF(conj(z))): pair partner sits at the
// SAME aligned position. Syncs S2/S5 removed: the B-read of any position and
// its C-write are always in the same quad (threads 4m+p / 4m+pe(p)) -> same
// warp -> ordered by program order. Planes processed in REVERSE order so the
// tail of col_fwd's output (still L2-resident) is read first.
__global__ void __launch_bounds__(256) k_row_fused() {
    __shared__ float2 sb[4 * FSTR];
    int tid = threadIdx.x;
    int f = tid >> 6, t = tid & 63;
    int m = t >> 2, e = t & 3;
    int pe = ((e & 1) << 1) | ((e >> 1) & 1);
    int w = f >> 1, h = f & 1;
    int bx = blockIdx.x;
    size_t pb = (size_t)(gridDim.y - 1 - blockIdx.y) << 20;   // reverse order
    int U = 2 * bx + w;
    int row = (U == 0) ? (h ? 2 : 0) : dr4(h ? 1024 - U : U);
    bool legacy = (bx == 0 && w == 0);                 // rows {0,512}
    bool cj = (h == 1) && !legacy;                     // conjugate-trick slot
    float2* buf = sb + f * FSTR;
    size_t gbase = pb + ((size_t)row << 10);
    float2 x[16];
    #pragma unroll
    for (int k=0;k<16;k++){
        x[k] = g_Z[gbase + t + 64*k];
        if (cj) x[k].y = -x[k].y;
    }
    dif_A(x, t);
    #pragma unroll
    for (int k=0;k<16;k++) buf[PHYS(t+64*k)] = x[k];
    __syncthreads();                                   // S1
    #pragma unroll
    for (int j=0;j<16;j++){ int a=j>>2,b=j&3; x[j]=buf[PHYS(64*m+16*a+4*b+e)]; }
    dif_B(x, e);
    // (no sync: C-writes below hit positions whose B-readers are in-quad)
    #pragma unroll
    for (int j=0;j<16;j++){
        int a=j>>2, b=j&3;
        float2 v = difC<1, 2>(x[j], e);
        if (cj) v.y = -v.y;                            // slot holds Z_-U(-c) at P
        buf[PHYS(64*m+16*a+4*b+pe)] = v;
    }
    __syncthreads();                                   // S3
    // ---- aligned Wiener: partner at the SAME position in the odd slot ----
    for (int l = tid; l < 2048; l += 256) {
        int ww = l >> 10, p = l & 1023;
        if (bx == 0 && ww == 0) continue;              // legacy handled below
        int Ue = 2 * bx + ww;
        int rA = dr4(Ue);
        float2 v1, v2;
        wiener_pair(sb[(2*ww)*FSTR + PHYS(p)], sb[(2*ww+1)*FSTR + PHYS(p)],
                    (rA << 10) + p, v1, v2);
        sb[(2*ww)*FSTR + PHYS(p)]   = v1;
        sb[(2*ww+1)*FSTR + PHYS(p)] = v2;
    }
    if (bx == 0) {                                     // rows {0,512}: self-mirrored
        for (int l = tid; l < 1026; l += 256) {
            int rw = (l >= 513); int cf = l - 513 * rw;
            int sc = dr4(cf), smc = dr4((1024 - cf) & 1023);
            float2 v1, v2;
            int rA = rw ? 2 : 0;
            wiener_pair(sb[rw*FSTR + PHYS(sc)], sb[rw*FSTR + PHYS(smc)],
                        (rA << 10) + sc, v1, v2);
            sb[rw*FSTR + PHYS(sc)]  = v1;
            sb[rw*FSTR + PHYS(smc)] = v2;
        }
    }
    __syncthreads();                                   // S4
    #pragma unroll
    for (int j=0;j<16;j++){
        int a=j>>2, b=j&3;
        float2 v = buf[PHYS(64*m+16*a+4*b+e)];
        if (cj) v.y = -v.y;                            // conj before inverse
        x[j] = ditC<1, 2>(v, e);
    }
    dit_B(x, pe);
    // (no sync: pe-writes below hit positions whose e-readers are in-quad)
    #pragma unroll
    for (int j=0;j<16;j++){ int a=j>>2,b=j&3; buf[PHYS(64*m+16*a+4*b+pe)] = x[j]; }
    __syncthreads();                                   // S6
    #pragma unroll
    for (int k=0;k<16;k++) x[k] = buf[PHYS(t+64*k)];
    dit_A(x, t);
    #pragma unroll
    for (int k=0;k<16;k++){
        float2 v = x[k];
        if (cj) v.y = -v.y;                            // conj after inverse
        g_Z[gbase + t + 64*k] = v;
    }
}

// ---------------- pass 3: column DIT + unpack real/imag (8 cols) --------
__global__ void __launch_bounds__(512) k_col_inv(float* __restrict__ out) {
    extern __shared__ float2 sb[];
    int tid = threadIdx.x;
    int f = tid & 7, t = tid >> 3;
    int m = t >> 2, e = t & 3;
    size_t pb = (size_t)blockIdx.y << 20;
    float* oa = out + (pb << 1);
    float* ob = oa + (1u << 20);
    int c = (blockIdx.x << 3) + f;
    float2* buf = sb + f * FSTR;
    float2 x[16];
    #pragma unroll
    for (int j=0;j<16;j++){
        int a=j>>2, b=j&3;
        float2 v = g_Z[pb + ((size_t)(64*m+16*a+4*b+e) << 10) + c];
        x[j] = ditC<8, 16>(v, e);
    }
    int pe = ((e & 1) << 1) | ((e >> 1) & 1);
    dit_B(x, pe);
    #pragma unroll
    for (int j=0;j<16;j++){ int a=j>>2,b=j&3; buf[PHYS(64*m+16*a+4*b+pe)] = x[j]; }
    __syncthreads();
    #pragma unroll
    for (int k=0;k<16;k++) x[k] = buf[PHYS(t+64*k)];
    dit_A(x, t);
    #pragma unroll
    for (int k=0;k<16;k++){
        int r = t + 64*k;
        oa[(r<<10)+c] = x[k].x * INVN;
        ob[(r<<10)+c] = x[k].y * INVN;
    }
}

extern "C" void kernel_launch(void* const* d_in, const int* in_sizes, int n_in,
                              void* d_out, int out_size) {
    const float* y   = (const float*)d_in[0];
    const float* psf = (const float*)d_in[1];
    float* out = (float*)d_out;

    int imgs = in_sizes[0] >> 20;                      // 24
    int planes = imgs >> 1;                            // 12 packed complex planes
    if (planes > MAXPLANES) planes = MAXPLANES;
    int kh = (int)lroundf(sqrtf((float)in_sizes[1])); // 25

    const int colSmem = 8 * FSTR * (int)sizeof(float2);   // ~68 KB dynamic
    cudaFuncSetAttribute(k_colP_fast,    cudaFuncAttributeMaxDynamicSharedMemorySize, colSmem);
    cudaFuncSetAttribute(k_rowP_ri_fast, cudaFuncAttributeMaxDynamicSharedMemorySize, colSmem);
    cudaFuncSetAttribute(k_col_fwd,      cudaFuncAttributeMaxDynamicSharedMemorySize, colSmem);
    cudaFuncSetAttribute(k_col_inv,      cudaFuncAttributeMaxDynamicSharedMemorySize, colSmem);

    // OTF -> RI + PSD (compact band; stored digit-reversed layout)
    k_init<<<4, 256>>>();
    k_colP_fast<<<4, 512, colSmem>>>(psf, kh);
    k_rowP_ri_fast<<<128, 512, colSmem>>>();

    // main: col DIF -> fused(row DIF, aligned Wiener, row DIT) -> col DIT
    k_col_fwd<<<dim3(128, planes), 512, colSmem>>>(y);
    k_row_fused<<<dim3(256, planes), 256>>>();
    k_col_inv<<<dim3(128, planes), 512, colSmem>>>(out);
}